// round 13
// baseline (speedup 1.0000x reference)
#include <cuda_runtime.h>
#include <cstdint>

#define NT      512
#define PIX     16384
#define NB      64
#define NSAMP   1024
#define NV      778
#define NPAIR   389      // NV/2
#define NVB     (NB * NV)
#define DGRID   384      // 256 A-blocks + 128 B-blocks

typedef unsigned long long ull;

// ---------------- device scratch (no allocations allowed) ----------------
// Zero-initialized at load; invariants restored every run:
//   g_vminb set +inf by kC; g_sacc/g_vacc/g_adone/g_done reset by k_dist tails.
__device__ uint32_t g_keys[NB * PIX];            // 4 MB: per-pixel keys (0 = invalid)
__device__ float4   g_samp[NB * NSAMP];          // xyz + 0.5*|s|^2
__device__ uint32_t g_vminb[NVB];                // bits of d2min (>=0), atomicMin
__device__ ull      g_sacc;                      // fixed-point sum of sample mins
__device__ ull      g_vacc;                      // fixed-point sum of vert mins
__device__ uint32_t g_adone[NB];                 // per-batch A-block counters
__device__ uint32_t g_done;                      // global completion counter

// ---------------- tf32 round-to-nearest-even (cuBLAS operand rounding) ----
__device__ __forceinline__ float tf32r(float x) {
    uint32_t u = __float_as_uint(x);
    uint32_t r = (u + 0xFFFu + ((u >> 13) & 1u)) & ~0x1FFFu;
    return __uint_as_float(r);
}

// ---------------- packed f32x2 helpers ----------------
__device__ __forceinline__ ull pk2(float lo, float hi) {
    ull r;
    asm("mov.b64 %0, {%1, %2};" : "=l"(r) : "f"(lo), "f"(hi));
    return r;
}

__device__ __forceinline__ float2 dot3p(ull nx, ull X, ull ny, ull Y,
                                        ull nz, ull Z, ull W) {
    float lo, hi;
    asm("{\n\t"
        ".reg .b64 t;\n\t"
        "fma.rn.f32x2 t, %2, %3, %4;\n\t"
        "fma.rn.f32x2 t, %5, %6, t;\n\t"
        "fma.rn.f32x2 t, %7, %8, t;\n\t"
        "mov.b64 {%0, %1}, t;\n\t"
        "}"
        : "=f"(lo), "=f"(hi)
        : "l"(nz), "l"(Z), "l"(W), "l"(ny), "l"(Y), "l"(nx), "l"(X));
    return make_float2(lo, hi);
}

// ------- threefry2x32-20, JAX partitionable counter-mode, key = (0,1) -----
__device__ __forceinline__ uint32_t rotl32(uint32_t x, uint32_t d) {
    return (x << d) | (x >> (32u - d));
}

__device__ __forceinline__ uint32_t threefry_bits_part(uint32_t e) {
    uint32_t x0 = 0u;
    uint32_t x1 = e;
    const uint32_t k0 = 0u, k1 = 1u;
    const uint32_t k2 = 0x1BD11BDAu ^ k0 ^ k1;
    x0 += k0; x1 += k1;
#define TF_RND(r) { x0 += x1; x1 = rotl32(x1, r) ^ x0; }
    TF_RND(13u) TF_RND(15u) TF_RND(26u) TF_RND(6u)
    x0 += k1; x1 += k2 + 1u;
    TF_RND(17u) TF_RND(29u) TF_RND(16u) TF_RND(24u)
    x0 += k2; x1 += k0 + 2u;
    TF_RND(13u) TF_RND(15u) TF_RND(26u) TF_RND(6u)
    x0 += k0; x1 += k1 + 3u;
    TF_RND(17u) TF_RND(29u) TF_RND(16u) TF_RND(24u)
    x0 += k1; x1 += k2 + 4u;
    TF_RND(13u) TF_RND(15u) TF_RND(26u) TF_RND(6u)
    x0 += k2; x1 += k0 + 5u;
#undef TF_RND
    return x0 ^ x1;
}

// ---------------- pixel -> normalized xyz (+ 0.5*|s|^2) ----------------
__device__ __forceinline__ float4 pix_xyz4(int p, float imgval, const float* sp) {
    float tj = 2.0f * (float)(p & 127) / 127.0f - 1.0f;
    float ti = 2.0f * (float)(p >> 7)  / 127.0f - 1.0f;
    float u = (tj + 1.0f) * 64.0f;
    float v = (ti + 1.0f) * 64.0f;
    float d = imgval * sp[11] + sp[8];
    float ut = tf32r(u), vt = tf32r(v);
    float uw = fmaf(sp[0], ut, fmaf(sp[1], vt, sp[2]));
    float vw = fmaf(sp[3], ut, fmaf(sp[4], vt, sp[5]));
    float x = (uw - 320.0f) * d / 588.03f;
    float y = (vw - 240.0f) * d / 587.07f;   // FLIP = 1
    float xn = (x - sp[6]) / sp[9];
    float yn = (y - sp[7]) / sp[10];
    float zn = (d - sp[8]) / sp[11];
    float hs = 0.5f * (xn * xn + yn * yn + zn * zn);
    return make_float4(xn, yn, zn, hs);
}

// ===== KA: full-chip threefry, coalesced key store ONLY (grid 1024) =====
__global__ void __launch_bounds__(256)
kA(const float* __restrict__ real) {
    uint32_t gt = blockIdx.x * 256u + threadIdx.x;   // 0..262143
#pragma unroll
    for (int k = 0; k < 4; k++) {
        uint32_t e = gt + (uint32_t)k * 262144u;     // 0..2^20-1
        uint32_t bits = threefry_bits_part(e);
        bool valid = real[e] <= 0.99f;
        g_keys[e] = valid ? ((bits >> 9) | 0x800000u) : 0u;
    }
}

// ===== KC: per-batch smem histogram + threshold + scan emit (grid 64) =====
// also inits g_vminb to +inf for k_dist
__global__ void __launch_bounds__(NT)
kC(const float* __restrict__ real, const float* __restrict__ center,
   const float* __restrict__ Mmat, const float* __restrict__ cube) {
    extern __shared__ uint32_t smem_u32[];
    uint32_t* skey = smem_u32;          // PIX entries (64 KB)
    uint32_t* hist = smem_u32 + PIX;    // 4096 entries (16 KB)
    __shared__ uint32_t wsum[16];
    __shared__ uint32_t woff[17];
    __shared__ float    s_par[12];
    __shared__ uint32_t s_T, s_need, s_ntie;
    __shared__ uint32_t s_tie[64];

    int b = blockIdx.x;
    int tid = threadIdx.x;
    int lane = tid & 31;
    int wid = tid >> 5;

    if (tid == 0) {
        const float* Mb = Mmat + b * 9;
        double a00 = Mb[0], a01 = Mb[1], a02 = Mb[2];
        double a10 = Mb[3], a11 = Mb[4], a12 = Mb[5];
        double a20 = Mb[6], a21 = Mb[7], a22 = Mb[8];
        double det = a00 * (a11 * a22 - a12 * a21)
                   - a01 * (a10 * a22 - a12 * a20)
                   + a02 * (a10 * a21 - a11 * a20);
        double inv = 1.0 / det;
        s_par[0] = tf32r((float)( (a11 * a22 - a12 * a21) * inv));
        s_par[1] = tf32r((float)(-(a01 * a22 - a02 * a21) * inv));
        s_par[2] = tf32r((float)( (a01 * a12 - a02 * a11) * inv));
        s_par[3] = tf32r((float)(-(a10 * a22 - a12 * a20) * inv));
        s_par[4] = tf32r((float)( (a00 * a22 - a02 * a20) * inv));
        s_par[5] = tf32r((float)(-(a00 * a12 - a02 * a10) * inv));
        s_par[6] = center[b * 3 + 0];
        s_par[7] = center[b * 3 + 1];
        s_par[8] = center[b * 3 + 2];
        s_par[9]  = cube[b * 3 + 0] * 0.5f;
        s_par[10] = cube[b * 3 + 1] * 0.5f;
        s_par[11] = cube[b * 3 + 2] * 0.5f;
        s_ntie = 0;
    }
    // bulk-load this batch's keys (L2-resident) + zero histogram
    {
        const uint4* gk = (const uint4*)(g_keys + b * PIX);
        uint4* sk4 = (uint4*)skey;
        for (int i = tid; i < PIX / 4; i += NT) sk4[i] = gk[i];
        for (int i = tid; i < 4096; i += NT) hist[i] = 0u;
    }
    // init vert-min array for k_dist (full range, split across 64 CTAs)
    for (int i = b * NT + tid; i < NVB; i += NB * NT)
        g_vminb[i] = 0x7F800000u;
    __syncthreads();

    // ---- build histogram with smem atomics (valid keys have marker bit) --
    for (int p = tid; p < PIX; p += NT) {
        uint32_t sk = skey[p];
        if (sk) atomicAdd(&hist[(sk >> 11) - 4096u], 1u);
    }
    __syncthreads();

    // ---- threshold via shfl prefix over 512 per-thread sums (contiguous) --
    {
        uint32_t c = 0;
#pragma unroll
        for (int k = 0; k < 8; k++) c += hist[tid * 8 + k];
        uint32_t p = c;
#pragma unroll
        for (int d = 1; d < 32; d <<= 1) {
            uint32_t n = __shfl_up_sync(0xFFFFFFFFu, p, d);
            if (lane >= d) p += n;
        }
        if (lane == 31) wsum[wid] = p;
        __syncthreads();
        if (wid == 0) {
            uint32_t w = (lane < 16) ? wsum[lane] : 0u;
            uint32_t q = w;
#pragma unroll
            for (int d = 1; d < 16; d <<= 1) {
                uint32_t n = __shfl_up_sync(0xFFFFFFFFu, q, d);
                if (lane >= d) q += n;
            }
            if (lane < 16) woff[lane] = q - w;
            if (lane == 15) woff[16] = q;
        }
        __syncthreads();
        uint32_t Pincl = p + woff[wid];
        uint32_t above = woff[16] - Pincl;
        uint32_t S = above + c;
        const uint32_t target = NSAMP;
        if (above < target && S >= target) {
            uint32_t cgt = above;
            for (int k = 7; k >= 0; k--) {
                uint32_t h = hist[tid * 8 + k];
                if (cgt + h >= target) {
                    s_T = (uint32_t)(tid * 8 + k);
                    s_need = target - cgt;
                    break;
                }
                cgt += h;
            }
        }
        __syncthreads();
    }
    uint32_t thrB = s_T + 4096u;          // threshold bucket in (sk>>11) space
    uint32_t need = s_need;

    const float* img = real + b * PIX;
    float4* out = g_samp + b * NSAMP;

    // ---- deterministic scan compaction over contiguous 32-pixel ranges ----
    const int PPT = PIX / NT;  // 32
    int base = tid * PPT;
    uint32_t cnt = 0;
#pragma unroll 4
    for (int k = 0; k < PPT; k++) cnt += ((skey[base + k] >> 11) > thrB) ? 1u : 0u;
    {
        uint32_t p = cnt;
#pragma unroll
        for (int d = 1; d < 32; d <<= 1) {
            uint32_t n = __shfl_up_sync(0xFFFFFFFFu, p, d);
            if (lane >= d) p += n;
        }
        if (lane == 31) wsum[wid] = p;
        __syncthreads();
        if (wid == 0) {
            uint32_t w = (lane < 16) ? wsum[lane] : 0u;
            uint32_t q = w;
#pragma unroll
            for (int d = 1; d < 16; d <<= 1) {
                uint32_t n = __shfl_up_sync(0xFFFFFFFFu, q, d);
                if (lane >= d) q += n;
            }
            if (lane < 16) woff[lane] = q - w;
        }
        __syncthreads();
        uint32_t off = (p - cnt) + woff[wid];    // exclusive global offset
        for (int k = 0; k < PPT; k++) {
            int pp = base + k;
            uint32_t bkt = skey[pp] >> 11;
            if (bkt > thrB) {
                out[off++] = pix_xyz4(pp, img[pp], s_par);
            } else if (bkt == thrB) {
                uint32_t pos = atomicAdd(&s_ntie, 1u);
                if (pos < 64u) s_tie[pos] = (uint32_t)pp;
            }
        }
    }
    __syncthreads();

    // boundary bucket: sort by (full key desc, index asc); take `need`
    if (tid == 0) {
        uint32_t n = s_ntie < 64u ? s_ntie : 64u;
        for (uint32_t i = 1; i < n; i++) {
            uint32_t pi = s_tie[i];
            uint32_t ki = skey[pi];
            int j = (int)i - 1;
            while (j >= 0) {
                uint32_t pj = s_tie[j];
                uint32_t kj = skey[pj];
                if (kj < ki || (kj == ki && pj > pi)) {
                    s_tie[j + 1] = pj; j--;
                } else break;
            }
            s_tie[j + 1] = pi;
        }
        uint32_t start = NSAMP - need;
        for (uint32_t i = 0; i < need && i < n; i++) {
            uint32_t pp = s_tie[i];
            out[start + i] = pix_xyz4((int)pp, img[pp], s_par);
        }
    }
}

// ===== K_DIST: blocks 0..255 vert pass (A); 256..383 sample pass (B);
//       per-batch tail sums vert mins; global tail writes the output =====
__global__ void __launch_bounds__(256)
k_dist(const float* __restrict__ verts, float* __restrict__ outp) {
    __shared__ ull   shbuf[4 * NPAIR];   // A: 4x128 packed samples; B: packed verts
    __shared__ float pm[256];
    __shared__ bool  isLastA, isLastG;

    int tid = threadIdx.x;

    if (blockIdx.x < 256) {
        // -------- A: per-vert min over a 256-sample chunk --------
        int blk = blockIdx.x;
        int b = blk >> 2;
        int chunk = blk & 3;
        ull* px = shbuf;         // 128
        ull* py = shbuf + 128;
        ull* pz = shbuf + 256;
        ull* pw = shbuf + 384;

        const float4* sp = g_samp + b * NSAMP + chunk * 256;
        if (tid < 128) {
            float4 f0 = sp[2 * tid];
            float4 f1 = sp[2 * tid + 1];
            px[tid] = pk2(f0.x, f1.x);
            py[tid] = pk2(f0.y, f1.y);
            pz[tid] = pk2(f0.z, f1.z);
            pw[tid] = pk2(f0.w, f1.w);
        }
        __syncthreads();

        if (tid < 195) {
            const float* vb = verts + b * NV * 3;
            ull nx[4], ny[4], nz[4];
            float hw[4];
            int vidx[4];
#pragma unroll
            for (int k = 0; k < 4; k++) {
                int v = 4 * tid + k;
                vidx[k] = v < NV ? v : NV - 1;
                float x = vb[3 * vidx[k]], y = vb[3 * vidx[k] + 1], z = vb[3 * vidx[k] + 2];
                nx[k] = pk2(-x, -x);
                ny[k] = pk2(-y, -y);
                nz[k] = pk2(-z, -z);
                hw[k] = 0.5f * (x * x + y * y + z * z);
            }
            float ml[4] = {1e30f, 1e30f, 1e30f, 1e30f};
            float mh[4] = {1e30f, 1e30f, 1e30f, 1e30f};
#pragma unroll 4
            for (int i = 0; i < 128; i++) {
                ull X = px[i], Y = py[i], Z = pz[i], W = pw[i];
#pragma unroll
                for (int k = 0; k < 4; k++) {
                    float2 d = dot3p(nx[k], X, ny[k], Y, nz[k], Z, W);
                    ml[k] = fminf(ml[k], d.x);
                    mh[k] = fminf(mh[k], d.y);
                }
            }
#pragma unroll
            for (int k = 0; k < 4; k++) {
                if (4 * tid + k < NV) {
                    float val = 2.0f * (fminf(ml[k], mh[k]) + hw[k]);  // >= 0
                    atomicMin(&g_vminb[b * NV + vidx[k]], __float_as_uint(val));
                }
            }
        }

        // ---- per-batch tail: last of the 4 A-blocks sums this batch ----
        __syncthreads();
        if (tid == 0) {
            __threadfence();
            uint32_t t = atomicAdd(&g_adone[b], 1u);
            isLastA = (t == 3u);
        }
        __syncthreads();
        if (isLastA) {
            __threadfence();   // acquire: other blocks' mins are visible
            float acc = 0.0f;
            for (int i = tid; i < NV; i += 256)
                acc += __uint_as_float(g_vminb[b * NV + i]);
            pm[tid] = acc;
            __syncthreads();
            for (int off = 128; off > 0; off >>= 1) {
                if (tid < off) pm[tid] += pm[tid + off];
                __syncthreads();
            }
            if (tid == 0) {
                g_adone[b] = 0u;               // restore for next replay
                double v = (double)pm[0];
                if (v < 0.0) v = 0.0;
                atomicAdd(&g_vacc, (ull)(v * 4294967296.0));
            }
        }
    } else {
        // -------- B: per-sample min over ALL verts, 2 samples/thread --------
        int blk = blockIdx.x - 256;
        int b = blk >> 1;
        int half = blk & 1;
        ull* vx = shbuf;               // NPAIR each
        ull* vy = shbuf + NPAIR;
        ull* vz = shbuf + 2 * NPAIR;
        ull* vw = shbuf + 3 * NPAIR;

        const float* vb = verts + b * NV * 3;
        for (int j = tid; j < NPAIR; j += 256) {
            float ax = vb[6 * j],     ay = vb[6 * j + 1], az = vb[6 * j + 2];
            float bx = vb[6 * j + 3], by = vb[6 * j + 4], bz = vb[6 * j + 5];
            vx[j] = pk2(ax, bx);
            vy[j] = pk2(ay, by);
            vz[j] = pk2(az, bz);
            vw[j] = pk2(0.5f * (ax * ax + ay * ay + az * az),
                        0.5f * (bx * bx + by * by + bz * bz));
        }
        int s0 = half * 512 + tid;
        int s1 = half * 512 + 256 + tid;
        float4 me0 = g_samp[b * NSAMP + s0];
        float4 me1 = g_samp[b * NSAMP + s1];
        __syncthreads();

        ull ax0 = pk2(-me0.x, -me0.x), ay0 = pk2(-me0.y, -me0.y), az0 = pk2(-me0.z, -me0.z);
        ull ax1 = pk2(-me1.x, -me1.x), ay1 = pk2(-me1.y, -me1.y), az1 = pk2(-me1.z, -me1.z);
        float m0a = 1e30f, m0b = 1e30f, m1a = 1e30f, m1b = 1e30f;
#pragma unroll 4
        for (int j = 0; j < NPAIR; j++) {
            ull X = vx[j], Y = vy[j], Z = vz[j], W = vw[j];
            float2 d0 = dot3p(ax0, X, ay0, Y, az0, Z, W);
            float2 d1 = dot3p(ax1, X, ay1, Y, az1, Z, W);
            m0a = fminf(m0a, d0.x); m0b = fminf(m0b, d0.y);
            m1a = fminf(m1a, d1.x); m1b = fminf(m1b, d1.y);
        }
        float sum = 2.0f * (fminf(m0a, m0b) + me0.w)
                  + 2.0f * (fminf(m1a, m1b) + me1.w);

        pm[tid] = sum;
        __syncthreads();
        for (int off = 128; off > 0; off >>= 1) {
            if (tid < off) pm[tid] += pm[tid + off];
            __syncthreads();
        }
        if (tid == 0) {
            double v = (double)pm[0];
            if (v < 0.0) v = 0.0;
            atomicAdd(&g_sacc, (ull)(v * 4294967296.0));
        }
    }

    // -------- global completion: last of all 384 blocks writes output ------
    __syncthreads();
    if (tid == 0) {
        __threadfence();
        uint32_t t = atomicAdd(&g_done, 1u);
        isLastG = (t == DGRID - 1u);
    }
    __syncthreads();
    if (isLastG && tid == 0) {
        __threadfence();
        double s = (double)g_sacc * (1.0 / 4294967296.0);
        double v = (double)g_vacc * (1.0 / 4294967296.0);
        outp[0] = (float)(s / (double)(NB * NSAMP)) +
                  (float)(v / (double)(NB * NV));
        g_sacc = 0ull;                         // restore for next replay
        g_vacc = 0ull;
        g_done = 0u;
    }
}

// ======================== launch ========================
extern "C" void kernel_launch(void* const* d_in, const int* in_sizes, int n_in,
                              void* d_out, int out_size) {
    const float* real   = (const float*)d_in[0];
    // d_in[1] synth unused, d_in[3] faces unused
    const float* verts  = (const float*)d_in[2];
    const float* center = (const float*)d_in[4];
    const float* Mmat   = (const float*)d_in[5];
    const float* cube   = (const float*)d_in[6];

    size_t smemC = (size_t)(PIX + 4096) * sizeof(uint32_t);  // 80 KB dynamic
    cudaFuncSetAttribute(kC, cudaFuncAttributeMaxDynamicSharedMemorySize,
                         (int)smemC);

    kA<<<1024, 256>>>(real);
    kC<<<NB, NT, smemC>>>(real, center, Mmat, cube);
    k_dist<<<DGRID, 256>>>(verts, (float*)d_out);
}

// round 14
// speedup vs baseline: 1.0336x; 1.0336x over previous
#include <cuda_runtime.h>
#include <cstdint>

#define NT      512
#define PIX     16384
#define NB      64
#define NSAMP   1024
#define NV      778
#define NPAIR   389      // NV/2
#define NVB     (NB * NV)
#define DGRID   384      // 256 A-blocks + 128 B-blocks

typedef unsigned long long ull;

// ---------------- device scratch (no allocations allowed) ----------------
// Zero-initialized at load; invariants restored every run:
//   g_vminb set +inf by kC; g_sacc/g_vacc/g_adone/g_done reset by k_dist tails.
__device__ uint32_t g_keys[NB * PIX];            // 4 MB: per-pixel keys (0 = invalid)
__device__ float4   g_samp[NB * NSAMP];          // xyz + 0.5*|s|^2
__device__ uint32_t g_vminb[NVB];                // bits of d2min (>=0), atomicMin
__device__ ull      g_sacc;                      // fixed-point sum of sample mins
__device__ ull      g_vacc;                      // fixed-point sum of vert mins
__device__ uint32_t g_adone[NB];                 // per-batch A-block counters
__device__ uint32_t g_done;                      // global completion counter

// ---------------- tf32 round-to-nearest-even (cuBLAS operand rounding) ----
__device__ __forceinline__ float tf32r(float x) {
    uint32_t u = __float_as_uint(x);
    uint32_t r = (u + 0xFFFu + ((u >> 13) & 1u)) & ~0x1FFFu;
    return __uint_as_float(r);
}

// ---------------- packed f32x2 helpers ----------------
__device__ __forceinline__ ull pk2(float lo, float hi) {
    ull r;
    asm("mov.b64 %0, {%1, %2};" : "=l"(r) : "f"(lo), "f"(hi));
    return r;
}

__device__ __forceinline__ float2 dot3p(ull nx, ull X, ull ny, ull Y,
                                        ull nz, ull Z, ull W) {
    float lo, hi;
    asm("{\n\t"
        ".reg .b64 t;\n\t"
        "fma.rn.f32x2 t, %2, %3, %4;\n\t"
        "fma.rn.f32x2 t, %5, %6, t;\n\t"
        "fma.rn.f32x2 t, %7, %8, t;\n\t"
        "mov.b64 {%0, %1}, t;\n\t"
        "}"
        : "=f"(lo), "=f"(hi)
        : "l"(nz), "l"(Z), "l"(W), "l"(ny), "l"(Y), "l"(nx), "l"(X));
    return make_float2(lo, hi);
}

// ------- threefry2x32-20, JAX partitionable counter-mode, key = (0,1) -----
__device__ __forceinline__ uint32_t rotl32(uint32_t x, uint32_t d) {
    return (x << d) | (x >> (32u - d));
}

__device__ __forceinline__ uint32_t threefry_bits_part(uint32_t e) {
    uint32_t x0 = 0u;
    uint32_t x1 = e;
    const uint32_t k0 = 0u, k1 = 1u;
    const uint32_t k2 = 0x1BD11BDAu ^ k0 ^ k1;
    x0 += k0; x1 += k1;
#define TF_RND(r) { x0 += x1; x1 = rotl32(x1, r) ^ x0; }
    TF_RND(13u) TF_RND(15u) TF_RND(26u) TF_RND(6u)
    x0 += k1; x1 += k2 + 1u;
    TF_RND(17u) TF_RND(29u) TF_RND(16u) TF_RND(24u)
    x0 += k2; x1 += k0 + 2u;
    TF_RND(13u) TF_RND(15u) TF_RND(26u) TF_RND(6u)
    x0 += k0; x1 += k1 + 3u;
    TF_RND(17u) TF_RND(29u) TF_RND(16u) TF_RND(24u)
    x0 += k1; x1 += k2 + 4u;
    TF_RND(13u) TF_RND(15u) TF_RND(26u) TF_RND(6u)
    x0 += k2; x1 += k0 + 5u;
#undef TF_RND
    return x0 ^ x1;
}

// ---------------- pixel -> normalized xyz (+ 0.5*|s|^2) ----------------
__device__ __forceinline__ float4 pix_xyz4(int p, float imgval, const float* sp) {
    float tj = 2.0f * (float)(p & 127) / 127.0f - 1.0f;
    float ti = 2.0f * (float)(p >> 7)  / 127.0f - 1.0f;
    float u = (tj + 1.0f) * 64.0f;
    float v = (ti + 1.0f) * 64.0f;
    float d = imgval * sp[11] + sp[8];
    float ut = tf32r(u), vt = tf32r(v);
    float uw = fmaf(sp[0], ut, fmaf(sp[1], vt, sp[2]));
    float vw = fmaf(sp[3], ut, fmaf(sp[4], vt, sp[5]));
    float x = (uw - 320.0f) * d / 588.03f;
    float y = (vw - 240.0f) * d / 587.07f;   // FLIP = 1
    float xn = (x - sp[6]) / sp[9];
    float yn = (y - sp[7]) / sp[10];
    float zn = (d - sp[8]) / sp[11];
    float hs = 0.5f * (xn * xn + yn * yn + zn * zn);
    return make_float4(xn, yn, zn, hs);
}

// ===== KA: full-chip threefry, coalesced key store ONLY (grid 1024) =====
__global__ void __launch_bounds__(256)
kA(const float* __restrict__ real) {
    uint32_t gt = blockIdx.x * 256u + threadIdx.x;   // 0..262143
#pragma unroll
    for (int k = 0; k < 4; k++) {
        uint32_t e = gt + (uint32_t)k * 262144u;     // 0..2^20-1
        uint32_t bits = threefry_bits_part(e);
        bool valid = real[e] <= 0.99f;
        g_keys[e] = valid ? ((bits >> 9) | 0x800000u) : 0u;
    }
}

// ===== KC: per-batch select, keys kept in REGISTERS (grid 64) =====
// also inits g_vminb to +inf for k_dist
__global__ void __launch_bounds__(NT)
kC(const float* __restrict__ real, const float* __restrict__ center,
   const float* __restrict__ Mmat, const float* __restrict__ cube) {
    __shared__ uint32_t hist[4096];
    __shared__ uint32_t wsum[16];
    __shared__ uint32_t woff[17];
    __shared__ float    s_par[12];
    __shared__ uint32_t s_T, s_need, s_ntie;
    __shared__ ull      s_tie[64];

    int b = blockIdx.x;
    int tid = threadIdx.x;
    int lane = tid & 31;
    int wid = tid >> 5;

    if (tid == 0) {
        const float* Mb = Mmat + b * 9;
        double a00 = Mb[0], a01 = Mb[1], a02 = Mb[2];
        double a10 = Mb[3], a11 = Mb[4], a12 = Mb[5];
        double a20 = Mb[6], a21 = Mb[7], a22 = Mb[8];
        double det = a00 * (a11 * a22 - a12 * a21)
                   - a01 * (a10 * a22 - a12 * a20)
                   + a02 * (a10 * a21 - a11 * a20);
        double inv = 1.0 / det;
        s_par[0] = tf32r((float)( (a11 * a22 - a12 * a21) * inv));
        s_par[1] = tf32r((float)(-(a01 * a22 - a02 * a21) * inv));
        s_par[2] = tf32r((float)( (a01 * a12 - a02 * a11) * inv));
        s_par[3] = tf32r((float)(-(a10 * a22 - a12 * a20) * inv));
        s_par[4] = tf32r((float)( (a00 * a22 - a02 * a20) * inv));
        s_par[5] = tf32r((float)(-(a00 * a12 - a02 * a10) * inv));
        s_par[6] = center[b * 3 + 0];
        s_par[7] = center[b * 3 + 1];
        s_par[8] = center[b * 3 + 2];
        s_par[9]  = cube[b * 3 + 0] * 0.5f;
        s_par[10] = cube[b * 3 + 1] * 0.5f;
        s_par[11] = cube[b * 3 + 2] * 0.5f;
        s_ntie = 0;
    }
    for (int i = tid; i < 4096; i += NT) hist[i] = 0u;
    // init vert-min array for k_dist (full range, split across 64 CTAs)
    for (int i = b * NT + tid; i < NVB; i += NB * NT)
        g_vminb[i] = 0x7F800000u;
    __syncthreads();

    // ---- load this thread's 32 contiguous keys into registers (8x LDG.128),
    //      fuse histogram build over them ----
    const uint4* gk4 = (const uint4*)(g_keys + b * PIX);
    uint4 kr[8];
#pragma unroll
    for (int k = 0; k < 8; k++) kr[k] = gk4[tid * 8 + k];
#pragma unroll
    for (int k = 0; k < 8; k++) {
        uint32_t a = kr[k].x, c = kr[k].y, d = kr[k].z, e = kr[k].w;
        if (a) atomicAdd(&hist[(a >> 11) - 4096u], 1u);
        if (c) atomicAdd(&hist[(c >> 11) - 4096u], 1u);
        if (d) atomicAdd(&hist[(d >> 11) - 4096u], 1u);
        if (e) atomicAdd(&hist[(e >> 11) - 4096u], 1u);
    }
    __syncthreads();

    // ---- threshold via shfl prefix over 512 per-thread sums (contiguous) --
    {
        uint32_t c = 0;
#pragma unroll
        for (int k = 0; k < 8; k++) c += hist[tid * 8 + k];
        uint32_t p = c;
#pragma unroll
        for (int d = 1; d < 32; d <<= 1) {
            uint32_t n = __shfl_up_sync(0xFFFFFFFFu, p, d);
            if (lane >= d) p += n;
        }
        if (lane == 31) wsum[wid] = p;
        __syncthreads();
        if (wid == 0) {
            uint32_t w = (lane < 16) ? wsum[lane] : 0u;
            uint32_t q = w;
#pragma unroll
            for (int d = 1; d < 16; d <<= 1) {
                uint32_t n = __shfl_up_sync(0xFFFFFFFFu, q, d);
                if (lane >= d) q += n;
            }
            if (lane < 16) woff[lane] = q - w;
            if (lane == 15) woff[16] = q;
        }
        __syncthreads();
        uint32_t Pincl = p + woff[wid];
        uint32_t above = woff[16] - Pincl;
        uint32_t S = above + c;
        const uint32_t target = NSAMP;
        if (above < target && S >= target) {
            uint32_t cgt = above;
            for (int k = 7; k >= 0; k--) {
                uint32_t h = hist[tid * 8 + k];
                if (cgt + h >= target) {
                    s_T = (uint32_t)(tid * 8 + k);
                    s_need = target - cgt;
                    break;
                }
                cgt += h;
            }
        }
        __syncthreads();
    }
    uint32_t thrB = s_T + 4096u;          // threshold bucket in (sk>>11) space
    uint32_t need = s_need;

    const float* img = real + b * PIX;
    float4* out = g_samp + b * NSAMP;

    // ---- count strictly-greater keys (from registers) ----
    uint32_t cnt = 0;
#pragma unroll
    for (int k = 0; k < 8; k++) {
        cnt += ((kr[k].x >> 11) > thrB) ? 1u : 0u;
        cnt += ((kr[k].y >> 11) > thrB) ? 1u : 0u;
        cnt += ((kr[k].z >> 11) > thrB) ? 1u : 0u;
        cnt += ((kr[k].w >> 11) > thrB) ? 1u : 0u;
    }
    {
        uint32_t p = cnt;
#pragma unroll
        for (int d = 1; d < 32; d <<= 1) {
            uint32_t n = __shfl_up_sync(0xFFFFFFFFu, p, d);
            if (lane >= d) p += n;
        }
        if (lane == 31) wsum[wid] = p;
        __syncthreads();
        if (wid == 0) {
            uint32_t w = (lane < 16) ? wsum[lane] : 0u;
            uint32_t q = w;
#pragma unroll
            for (int d = 1; d < 16; d <<= 1) {
                uint32_t n = __shfl_up_sync(0xFFFFFFFFu, q, d);
                if (lane >= d) q += n;
            }
            if (lane < 16) woff[lane] = q - w;
        }
        __syncthreads();
        uint32_t off = (p - cnt) + woff[wid];    // exclusive global offset
        int basep = tid * 32;
#pragma unroll
        for (int k = 0; k < 8; k++) {
            uint32_t ks[4] = {kr[k].x, kr[k].y, kr[k].z, kr[k].w};
#pragma unroll
            for (int c = 0; c < 4; c++) {
                uint32_t sk = ks[c];
                uint32_t bkt = sk >> 11;
                int pp = basep + k * 4 + c;
                if (bkt > thrB) {
                    out[off++] = pix_xyz4(pp, img[pp], s_par);
                } else if (bkt == thrB) {
                    uint32_t pos = atomicAdd(&s_ntie, 1u);
                    if (pos < 64u) s_tie[pos] = ((ull)sk << 14) | (uint32_t)pp;
                }
            }
        }
    }
    __syncthreads();

    // boundary bucket: sort by (full key desc, pixel asc); take `need`
    if (tid == 0) {
        uint32_t n = s_ntie < 64u ? s_ntie : 64u;
        for (uint32_t i = 1; i < n; i++) {
            ull e = s_tie[i];
            int j = (int)i - 1;
            while (j >= 0) {
                ull f = s_tie[j];
                bool before = ((e >> 14) > (f >> 14)) ||
                              ((e >> 14) == (f >> 14) &&
                               (e & 16383ull) < (f & 16383ull));
                if (before) { s_tie[j + 1] = f; j--; } else break;
            }
            s_tie[j + 1] = e;
        }
        uint32_t start = NSAMP - need;
        for (uint32_t i = 0; i < need && i < n; i++) {
            int pp = (int)(s_tie[i] & 16383ull);
            out[start + i] = pix_xyz4(pp, img[pp], s_par);
        }
    }
}

// ===== K_DIST: blocks 0..255 vert pass (A); 256..383 sample pass (B);
//       per-batch tail sums vert mins; global tail writes the output =====
__global__ void __launch_bounds__(256)
k_dist(const float* __restrict__ verts, float* __restrict__ outp) {
    __shared__ ull   shbuf[4 * NPAIR];   // A: 4x128 packed samples; B: packed verts
    __shared__ float svr[NV * 3];        // A: raw verts, coalesced staged
    __shared__ float pm[256];
    __shared__ bool  isLastA, isLastG;

    int tid = threadIdx.x;

    if (blockIdx.x < 256) {
        // -------- A: per-vert min over a 256-sample chunk --------
        int blk = blockIdx.x;
        int b = blk >> 2;
        int chunk = blk & 3;
        ull* px = shbuf;         // 128
        ull* py = shbuf + 128;
        ull* pz = shbuf + 256;
        ull* pw = shbuf + 384;

        // coalesced vert staging
        const float* vb = verts + b * NV * 3;
        for (int i = tid; i < NV * 3; i += 256) svr[i] = vb[i];

        const float4* sp = g_samp + b * NSAMP + chunk * 256;
        if (tid < 128) {
            float4 f0 = sp[2 * tid];
            float4 f1 = sp[2 * tid + 1];
            px[tid] = pk2(f0.x, f1.x);
            py[tid] = pk2(f0.y, f1.y);
            pz[tid] = pk2(f0.z, f1.z);
            pw[tid] = pk2(f0.w, f1.w);
        }
        __syncthreads();

        if (tid < 195) {
            ull nx[4], ny[4], nz[4];
            float hw[4];
            int vidx[4];
#pragma unroll
            for (int k = 0; k < 4; k++) {
                int v = 4 * tid + k;
                vidx[k] = v < NV ? v : NV - 1;
                float x = svr[3 * vidx[k]];
                float y = svr[3 * vidx[k] + 1];
                float z = svr[3 * vidx[k] + 2];
                nx[k] = pk2(-x, -x);
                ny[k] = pk2(-y, -y);
                nz[k] = pk2(-z, -z);
                hw[k] = 0.5f * (x * x + y * y + z * z);
            }
            float ml[4] = {1e30f, 1e30f, 1e30f, 1e30f};
            float mh[4] = {1e30f, 1e30f, 1e30f, 1e30f};
#pragma unroll 4
            for (int i = 0; i < 128; i++) {
                ull X = px[i], Y = py[i], Z = pz[i], W = pw[i];
#pragma unroll
                for (int k = 0; k < 4; k++) {
                    float2 d = dot3p(nx[k], X, ny[k], Y, nz[k], Z, W);
                    ml[k] = fminf(ml[k], d.x);
                    mh[k] = fminf(mh[k], d.y);
                }
            }
#pragma unroll
            for (int k = 0; k < 4; k++) {
                if (4 * tid + k < NV) {
                    float val = 2.0f * (fminf(ml[k], mh[k]) + hw[k]);  // >= 0
                    atomicMin(&g_vminb[b * NV + vidx[k]], __float_as_uint(val));
                }
            }
        }

        // ---- per-batch tail: last of the 4 A-blocks sums this batch ----
        __syncthreads();
        if (tid == 0) {
            __threadfence();
            uint32_t t = atomicAdd(&g_adone[b], 1u);
            isLastA = (t == 3u);
        }
        __syncthreads();
        if (isLastA) {
            __threadfence();   // acquire: other blocks' mins are visible
            float acc = 0.0f;
            for (int i = tid; i < NV; i += 256)
                acc += __uint_as_float(g_vminb[b * NV + i]);
            pm[tid] = acc;
            __syncthreads();
            for (int off = 128; off > 0; off >>= 1) {
                if (tid < off) pm[tid] += pm[tid + off];
                __syncthreads();
            }
            if (tid == 0) {
                g_adone[b] = 0u;               // restore for next replay
                double v = (double)pm[0];
                if (v < 0.0) v = 0.0;
                atomicAdd(&g_vacc, (ull)(v * 4294967296.0));
            }
        }
    } else {
        // -------- B: per-sample min over ALL verts, 2 samples/thread --------
        int blk = blockIdx.x - 256;
        int b = blk >> 1;
        int half = blk & 1;
        ull* vx = shbuf;               // NPAIR each
        ull* vy = shbuf + NPAIR;
        ull* vz = shbuf + 2 * NPAIR;
        ull* vw = shbuf + 3 * NPAIR;

        const float* vb = verts + b * NV * 3;
        for (int j = tid; j < NPAIR; j += 256) {
            float ax = vb[6 * j],     ay = vb[6 * j + 1], az = vb[6 * j + 2];
            float bx = vb[6 * j + 3], by = vb[6 * j + 4], bz = vb[6 * j + 5];
            vx[j] = pk2(ax, bx);
            vy[j] = pk2(ay, by);
            vz[j] = pk2(az, bz);
            vw[j] = pk2(0.5f * (ax * ax + ay * ay + az * az),
                        0.5f * (bx * bx + by * by + bz * bz));
        }
        int s0 = half * 512 + tid;
        int s1 = half * 512 + 256 + tid;
        float4 me0 = g_samp[b * NSAMP + s0];
        float4 me1 = g_samp[b * NSAMP + s1];
        __syncthreads();

        ull ax0 = pk2(-me0.x, -me0.x), ay0 = pk2(-me0.y, -me0.y), az0 = pk2(-me0.z, -me0.z);
        ull ax1 = pk2(-me1.x, -me1.x), ay1 = pk2(-me1.y, -me1.y), az1 = pk2(-me1.z, -me1.z);
        float m0a = 1e30f, m0b = 1e30f, m1a = 1e30f, m1b = 1e30f;
#pragma unroll 4
        for (int j = 0; j < NPAIR; j++) {
            ull X = vx[j], Y = vy[j], Z = vz[j], W = vw[j];
            float2 d0 = dot3p(ax0, X, ay0, Y, az0, Z, W);
            float2 d1 = dot3p(ax1, X, ay1, Y, az1, Z, W);
            m0a = fminf(m0a, d0.x); m0b = fminf(m0b, d0.y);
            m1a = fminf(m1a, d1.x); m1b = fminf(m1b, d1.y);
        }
        float sum = 2.0f * (fminf(m0a, m0b) + me0.w)
                  + 2.0f * (fminf(m1a, m1b) + me1.w);

        pm[tid] = sum;
        __syncthreads();
        for (int off = 128; off > 0; off >>= 1) {
            if (tid < off) pm[tid] += pm[tid + off];
            __syncthreads();
        }
        if (tid == 0) {
            double v = (double)pm[0];
            if (v < 0.0) v = 0.0;
            atomicAdd(&g_sacc, (ull)(v * 4294967296.0));
        }
    }

    // -------- global completion: last of all 384 blocks writes output ------
    __syncthreads();
    if (tid == 0) {
        __threadfence();
        uint32_t t = atomicAdd(&g_done, 1u);
        isLastG = (t == DGRID - 1u);
    }
    __syncthreads();
    if (isLastG && tid == 0) {
        __threadfence();
        double s = (double)g_sacc * (1.0 / 4294967296.0);
        double v = (double)g_vacc * (1.0 / 4294967296.0);
        outp[0] = (float)(s / (double)(NB * NSAMP)) +
                  (float)(v / (double)(NB * NV));
        g_sacc = 0ull;                         // restore for next replay
        g_vacc = 0ull;
        g_done = 0u;
    }
}

// ======================== launch ========================
extern "C" void kernel_launch(void* const* d_in, const int* in_sizes, int n_in,
                              void* d_out, int out_size) {
    const float* real   = (const float*)d_in[0];
    // d_in[1] synth unused, d_in[3] faces unused
    const float* verts  = (const float*)d_in[2];
    const float* center = (const float*)d_in[4];
    const float* Mmat   = (const float*)d_in[5];
    const float* cube   = (const float*)d_in[6];

    kA<<<1024, 256>>>(real);
    kC<<<NB, NT>>>(real, center, Mmat, cube);
    k_dist<<<DGRID, 256>>>(verts, (float*)d_out);
}

// round 15
// speedup vs baseline: 1.0718x; 1.0370x over previous
#include <cuda_runtime.h>
#include <cstdint>

#define NT      512
#define PIX     16384
#define NB      64
#define NSAMP   1024
#define NV      778
#define NPAIR   389      // NV/2
#define NVB     (NB * NV)
#define DGRID   384      // 256 A-blocks + 128 B-blocks

typedef unsigned long long ull;

// ---------------- device scratch (no allocations allowed) ----------------
// Zero-initialized at load; invariants restored every run:
//   g_vminb set +inf by kSel; g_sacc/g_vacc/g_adone/g_done reset by k_dist tails.
__device__ float4   g_samp[NB * NSAMP];          // xyz + 0.5*|s|^2
__device__ uint32_t g_vminb[NVB];                // bits of d2min (>=0), atomicMin
__device__ ull      g_sacc;                      // fixed-point sum of sample mins
__device__ ull      g_vacc;                      // fixed-point sum of vert mins
__device__ uint32_t g_adone[NB];                 // per-batch A-block counters
__device__ uint32_t g_done;                      // global completion counter

// ---------------- tf32 round-to-nearest-even (cuBLAS operand rounding) ----
__device__ __forceinline__ float tf32r(float x) {
    uint32_t u = __float_as_uint(x);
    uint32_t r = (u + 0xFFFu + ((u >> 13) & 1u)) & ~0x1FFFu;
    return __uint_as_float(r);
}

// ---------------- packed f32x2 helpers ----------------
__device__ __forceinline__ ull pk2(float lo, float hi) {
    ull r;
    asm("mov.b64 %0, {%1, %2};" : "=l"(r) : "f"(lo), "f"(hi));
    return r;
}

__device__ __forceinline__ float2 dot3p(ull nx, ull X, ull ny, ull Y,
                                        ull nz, ull Z, ull W) {
    float lo, hi;
    asm("{\n\t"
        ".reg .b64 t;\n\t"
        "fma.rn.f32x2 t, %2, %3, %4;\n\t"
        "fma.rn.f32x2 t, %5, %6, t;\n\t"
        "fma.rn.f32x2 t, %7, %8, t;\n\t"
        "mov.b64 {%0, %1}, t;\n\t"
        "}"
        : "=f"(lo), "=f"(hi)
        : "l"(nz), "l"(Z), "l"(W), "l"(ny), "l"(Y), "l"(nx), "l"(X));
    return make_float2(lo, hi);
}

// ------- threefry2x32-20, JAX partitionable counter-mode, key = (0,1) -----
__device__ __forceinline__ uint32_t rotl32(uint32_t x, uint32_t d) {
    return (x << d) | (x >> (32u - d));
}

__device__ __forceinline__ uint32_t threefry_bits_part(uint32_t e) {
    uint32_t x0 = 0u;
    uint32_t x1 = e;
    const uint32_t k0 = 0u, k1 = 1u;
    const uint32_t k2 = 0x1BD11BDAu ^ k0 ^ k1;
    x0 += k0; x1 += k1;
#define TF_RND(r) { x0 += x1; x1 = rotl32(x1, r) ^ x0; }
    TF_RND(13u) TF_RND(15u) TF_RND(26u) TF_RND(6u)
    x0 += k1; x1 += k2 + 1u;
    TF_RND(17u) TF_RND(29u) TF_RND(16u) TF_RND(24u)
    x0 += k2; x1 += k0 + 2u;
    TF_RND(13u) TF_RND(15u) TF_RND(26u) TF_RND(6u)
    x0 += k0; x1 += k1 + 3u;
    TF_RND(17u) TF_RND(29u) TF_RND(16u) TF_RND(24u)
    x0 += k1; x1 += k2 + 4u;
    TF_RND(13u) TF_RND(15u) TF_RND(26u) TF_RND(6u)
    x0 += k2; x1 += k0 + 5u;
#undef TF_RND
    return x0 ^ x1;
}

// ---------------- pixel -> normalized xyz (+ 0.5*|s|^2) ----------------
__device__ __forceinline__ float4 pix_xyz4(int p, float imgval, const float* sp) {
    float tj = 2.0f * (float)(p & 127) / 127.0f - 1.0f;
    float ti = 2.0f * (float)(p >> 7)  / 127.0f - 1.0f;
    float u = (tj + 1.0f) * 64.0f;
    float v = (ti + 1.0f) * 64.0f;
    float d = imgval * sp[11] + sp[8];
    float ut = tf32r(u), vt = tf32r(v);
    float uw = fmaf(sp[0], ut, fmaf(sp[1], vt, sp[2]));
    float vw = fmaf(sp[3], ut, fmaf(sp[4], vt, sp[5]));
    float x = (uw - 320.0f) * d / 588.03f;
    float y = (vw - 240.0f) * d / 587.07f;   // FLIP = 1
    float xn = (x - sp[6]) / sp[9];
    float yn = (y - sp[7]) / sp[10];
    float zn = (d - sp[8]) / sp[11];
    float hs = 0.5f * (xn * xn + yn * yn + zn * zn);
    return make_float4(xn, yn, zn, hs);
}

// ===== KSEL: fused threefry + per-batch select (grid 64) =====
// Keys computed IN REGISTERS (no global key array, no separate kernel).
// Also inits g_vminb to +inf for k_dist.
__global__ void __launch_bounds__(NT)
kSel(const float* __restrict__ real, const float* __restrict__ center,
     const float* __restrict__ Mmat, const float* __restrict__ cube) {
    __shared__ uint32_t hist[4096];
    __shared__ uint32_t wsum[16];
    __shared__ uint32_t woff[17];
    __shared__ float    s_par[12];
    __shared__ uint32_t s_T, s_need, s_ntie;
    __shared__ ull      s_tie[64];

    int b = blockIdx.x;
    int tid = threadIdx.x;
    int lane = tid & 31;
    int wid = tid >> 5;

    if (tid == 0) {
        const float* Mb = Mmat + b * 9;
        double a00 = Mb[0], a01 = Mb[1], a02 = Mb[2];
        double a10 = Mb[3], a11 = Mb[4], a12 = Mb[5];
        double a20 = Mb[6], a21 = Mb[7], a22 = Mb[8];
        double det = a00 * (a11 * a22 - a12 * a21)
                   - a01 * (a10 * a22 - a12 * a20)
                   + a02 * (a10 * a21 - a11 * a20);
        double inv = 1.0 / det;
        s_par[0] = tf32r((float)( (a11 * a22 - a12 * a21) * inv));
        s_par[1] = tf32r((float)(-(a01 * a22 - a02 * a21) * inv));
        s_par[2] = tf32r((float)( (a01 * a12 - a02 * a11) * inv));
        s_par[3] = tf32r((float)(-(a10 * a22 - a12 * a20) * inv));
        s_par[4] = tf32r((float)( (a00 * a22 - a02 * a20) * inv));
        s_par[5] = tf32r((float)(-(a00 * a12 - a02 * a10) * inv));
        s_par[6] = center[b * 3 + 0];
        s_par[7] = center[b * 3 + 1];
        s_par[8] = center[b * 3 + 2];
        s_par[9]  = cube[b * 3 + 0] * 0.5f;
        s_par[10] = cube[b * 3 + 1] * 0.5f;
        s_par[11] = cube[b * 3 + 2] * 0.5f;
        s_ntie = 0;
    }
    for (int i = tid; i < 4096; i += NT) hist[i] = 0u;
    // init vert-min array for k_dist (full range, split across 64 CTAs)
    for (int i = b * NT + tid; i < NVB; i += NB * NT)
        g_vminb[i] = 0x7F800000u;
    __syncthreads();

    // ---- compute this thread's 32 contiguous keys in registers:
    //      coalesced image load (float4) + threefry, fused histogram ----
    const float4* img4 = (const float4*)(real + b * PIX);
    uint4 kr[8];
    {
        uint32_t ebase = (uint32_t)(b * PIX + tid * 32);
#pragma unroll
        for (int k = 0; k < 8; k++) {
            float4 iv = img4[tid * 8 + k];
            uint32_t e0 = ebase + (uint32_t)(k * 4);
            uint32_t b0 = threefry_bits_part(e0);
            uint32_t b1 = threefry_bits_part(e0 + 1u);
            uint32_t b2 = threefry_bits_part(e0 + 2u);
            uint32_t b3 = threefry_bits_part(e0 + 3u);
            kr[k].x = (iv.x <= 0.99f) ? ((b0 >> 9) | 0x800000u) : 0u;
            kr[k].y = (iv.y <= 0.99f) ? ((b1 >> 9) | 0x800000u) : 0u;
            kr[k].z = (iv.z <= 0.99f) ? ((b2 >> 9) | 0x800000u) : 0u;
            kr[k].w = (iv.w <= 0.99f) ? ((b3 >> 9) | 0x800000u) : 0u;
            if (kr[k].x) atomicAdd(&hist[(kr[k].x >> 11) - 4096u], 1u);
            if (kr[k].y) atomicAdd(&hist[(kr[k].y >> 11) - 4096u], 1u);
            if (kr[k].z) atomicAdd(&hist[(kr[k].z >> 11) - 4096u], 1u);
            if (kr[k].w) atomicAdd(&hist[(kr[k].w >> 11) - 4096u], 1u);
        }
    }
    __syncthreads();

    // ---- threshold via shfl prefix over 512 per-thread sums (contiguous) --
    {
        uint32_t c = 0;
#pragma unroll
        for (int k = 0; k < 8; k++) c += hist[tid * 8 + k];
        uint32_t p = c;
#pragma unroll
        for (int d = 1; d < 32; d <<= 1) {
            uint32_t n = __shfl_up_sync(0xFFFFFFFFu, p, d);
            if (lane >= d) p += n;
        }
        if (lane == 31) wsum[wid] = p;
        __syncthreads();
        if (wid == 0) {
            uint32_t w = (lane < 16) ? wsum[lane] : 0u;
            uint32_t q = w;
#pragma unroll
            for (int d = 1; d < 16; d <<= 1) {
                uint32_t n = __shfl_up_sync(0xFFFFFFFFu, q, d);
                if (lane >= d) q += n;
            }
            if (lane < 16) woff[lane] = q - w;
            if (lane == 15) woff[16] = q;
        }
        __syncthreads();
        uint32_t Pincl = p + woff[wid];
        uint32_t above = woff[16] - Pincl;
        uint32_t S = above + c;
        const uint32_t target = NSAMP;
        if (above < target && S >= target) {
            uint32_t cgt = above;
            for (int k = 7; k >= 0; k--) {
                uint32_t h = hist[tid * 8 + k];
                if (cgt + h >= target) {
                    s_T = (uint32_t)(tid * 8 + k);
                    s_need = target - cgt;
                    break;
                }
                cgt += h;
            }
        }
        __syncthreads();
    }
    uint32_t thrB = s_T + 4096u;          // threshold bucket in (sk>>11) space
    uint32_t need = s_need;

    const float* img = real + b * PIX;
    float4* out = g_samp + b * NSAMP;

    // ---- count strictly-greater keys (from registers) ----
    uint32_t cnt = 0;
#pragma unroll
    for (int k = 0; k < 8; k++) {
        cnt += ((kr[k].x >> 11) > thrB) ? 1u : 0u;
        cnt += ((kr[k].y >> 11) > thrB) ? 1u : 0u;
        cnt += ((kr[k].z >> 11) > thrB) ? 1u : 0u;
        cnt += ((kr[k].w >> 11) > thrB) ? 1u : 0u;
    }
    {
        uint32_t p = cnt;
#pragma unroll
        for (int d = 1; d < 32; d <<= 1) {
            uint32_t n = __shfl_up_sync(0xFFFFFFFFu, p, d);
            if (lane >= d) p += n;
        }
        if (lane == 31) wsum[wid] = p;
        __syncthreads();
        if (wid == 0) {
            uint32_t w = (lane < 16) ? wsum[lane] : 0u;
            uint32_t q = w;
#pragma unroll
            for (int d = 1; d < 16; d <<= 1) {
                uint32_t n = __shfl_up_sync(0xFFFFFFFFu, q, d);
                if (lane >= d) q += n;
            }
            if (lane < 16) woff[lane] = q - w;
        }
        __syncthreads();
        uint32_t off = (p - cnt) + woff[wid];    // exclusive global offset
        int basep = tid * 32;
#pragma unroll
        for (int k = 0; k < 8; k++) {
            uint32_t ks[4] = {kr[k].x, kr[k].y, kr[k].z, kr[k].w};
#pragma unroll
            for (int c = 0; c < 4; c++) {
                uint32_t sk = ks[c];
                uint32_t bkt = sk >> 11;
                int pp = basep + k * 4 + c;
                if (bkt > thrB) {
                    out[off++] = pix_xyz4(pp, img[pp], s_par);
                } else if (bkt == thrB) {
                    uint32_t pos = atomicAdd(&s_ntie, 1u);
                    if (pos < 64u) s_tie[pos] = ((ull)sk << 14) | (uint32_t)pp;
                }
            }
        }
    }
    __syncthreads();

    // boundary bucket: sort by (full key desc, pixel asc); take `need`
    if (tid == 0) {
        uint32_t n = s_ntie < 64u ? s_ntie : 64u;
        for (uint32_t i = 1; i < n; i++) {
            ull e = s_tie[i];
            int j = (int)i - 1;
            while (j >= 0) {
                ull f = s_tie[j];
                bool before = ((e >> 14) > (f >> 14)) ||
                              ((e >> 14) == (f >> 14) &&
                               (e & 16383ull) < (f & 16383ull));
                if (before) { s_tie[j + 1] = f; j--; } else break;
            }
            s_tie[j + 1] = e;
        }
        uint32_t start = NSAMP - need;
        for (uint32_t i = 0; i < need && i < n; i++) {
            int pp = (int)(s_tie[i] & 16383ull);
            out[start + i] = pix_xyz4(pp, img[pp], s_par);
        }
    }
}

// ===== K_DIST: blocks 0..255 vert pass (A); 256..383 sample pass (B);
//       per-batch tail sums vert mins; global tail writes the output =====
__global__ void __launch_bounds__(256)
k_dist(const float* __restrict__ verts, float* __restrict__ outp) {
    __shared__ ull   shbuf[4 * NPAIR];   // A: 4x128 packed samples; B: packed verts
    __shared__ float svr[NV * 3];        // A: raw verts, coalesced staged
    __shared__ float pm[256];
    __shared__ bool  isLastA, isLastG;

    int tid = threadIdx.x;

    if (blockIdx.x < 256) {
        // -------- A: per-vert min over a 256-sample chunk --------
        int blk = blockIdx.x;
        int b = blk >> 2;
        int chunk = blk & 3;
        ull* px = shbuf;         // 128
        ull* py = shbuf + 128;
        ull* pz = shbuf + 256;
        ull* pw = shbuf + 384;

        // coalesced vert staging
        const float* vb = verts + b * NV * 3;
        for (int i = tid; i < NV * 3; i += 256) svr[i] = vb[i];

        const float4* sp = g_samp + b * NSAMP + chunk * 256;
        if (tid < 128) {
            float4 f0 = sp[2 * tid];
            float4 f1 = sp[2 * tid + 1];
            px[tid] = pk2(f0.x, f1.x);
            py[tid] = pk2(f0.y, f1.y);
            pz[tid] = pk2(f0.z, f1.z);
            pw[tid] = pk2(f0.w, f1.w);
        }
        __syncthreads();

        if (tid < 195) {
            ull nx[4], ny[4], nz[4];
            float hw[4];
            int vidx[4];
#pragma unroll
            for (int k = 0; k < 4; k++) {
                int v = 4 * tid + k;
                vidx[k] = v < NV ? v : NV - 1;
                float x = svr[3 * vidx[k]];
                float y = svr[3 * vidx[k] + 1];
                float z = svr[3 * vidx[k] + 2];
                nx[k] = pk2(-x, -x);
                ny[k] = pk2(-y, -y);
                nz[k] = pk2(-z, -z);
                hw[k] = 0.5f * (x * x + y * y + z * z);
            }
            float ml[4] = {1e30f, 1e30f, 1e30f, 1e30f};
            float mh[4] = {1e30f, 1e30f, 1e30f, 1e30f};
#pragma unroll 4
            for (int i = 0; i < 128; i++) {
                ull X = px[i], Y = py[i], Z = pz[i], W = pw[i];
#pragma unroll
                for (int k = 0; k < 4; k++) {
                    float2 d = dot3p(nx[k], X, ny[k], Y, nz[k], Z, W);
                    ml[k] = fminf(ml[k], d.x);
                    mh[k] = fminf(mh[k], d.y);
                }
            }
#pragma unroll
            for (int k = 0; k < 4; k++) {
                if (4 * tid + k < NV) {
                    float val = 2.0f * (fminf(ml[k], mh[k]) + hw[k]);  // >= 0
                    atomicMin(&g_vminb[b * NV + vidx[k]], __float_as_uint(val));
                }
            }
        }

        // ---- per-batch tail: last of the 4 A-blocks sums this batch ----
        __syncthreads();
        if (tid == 0) {
            __threadfence();
            uint32_t t = atomicAdd(&g_adone[b], 1u);
            isLastA = (t == 3u);
        }
        __syncthreads();
        if (isLastA) {
            __threadfence();   // acquire: other blocks' mins are visible
            float acc = 0.0f;
            for (int i = tid; i < NV; i += 256)
                acc += __uint_as_float(g_vminb[b * NV + i]);
            pm[tid] = acc;
            __syncthreads();
            for (int off = 128; off > 0; off >>= 1) {
                if (tid < off) pm[tid] += pm[tid + off];
                __syncthreads();
            }
            if (tid == 0) {
                g_adone[b] = 0u;               // restore for next replay
                double v = (double)pm[0];
                if (v < 0.0) v = 0.0;
                atomicAdd(&g_vacc, (ull)(v * 4294967296.0));
            }
        }
    } else {
        // -------- B: per-sample min over ALL verts, 2 samples/thread --------
        int blk = blockIdx.x - 256;
        int b = blk >> 1;
        int half = blk & 1;
        ull* vx = shbuf;               // NPAIR each
        ull* vy = shbuf + NPAIR;
        ull* vz = shbuf + 2 * NPAIR;
        ull* vw = shbuf + 3 * NPAIR;

        const float* vb = verts + b * NV * 3;
        for (int j = tid; j < NPAIR; j += 256) {
            float ax = vb[6 * j],     ay = vb[6 * j + 1], az = vb[6 * j + 2];
            float bx = vb[6 * j + 3], by = vb[6 * j + 4], bz = vb[6 * j + 5];
            vx[j] = pk2(ax, bx);
            vy[j] = pk2(ay, by);
            vz[j] = pk2(az, bz);
            vw[j] = pk2(0.5f * (ax * ax + ay * ay + az * az),
                        0.5f * (bx * bx + by * by + bz * bz));
        }
        int s0 = half * 512 + tid;
        int s1 = half * 512 + 256 + tid;
        float4 me0 = g_samp[b * NSAMP + s0];
        float4 me1 = g_samp[b * NSAMP + s1];
        __syncthreads();

        ull ax0 = pk2(-me0.x, -me0.x), ay0 = pk2(-me0.y, -me0.y), az0 = pk2(-me0.z, -me0.z);
        ull ax1 = pk2(-me1.x, -me1.x), ay1 = pk2(-me1.y, -me1.y), az1 = pk2(-me1.z, -me1.z);
        float m0a = 1e30f, m0b = 1e30f, m1a = 1e30f, m1b = 1e30f;
#pragma unroll 4
        for (int j = 0; j < NPAIR; j++) {
            ull X = vx[j], Y = vy[j], Z = vz[j], W = vw[j];
            float2 d0 = dot3p(ax0, X, ay0, Y, az0, Z, W);
            float2 d1 = dot3p(ax1, X, ay1, Y, az1, Z, W);
            m0a = fminf(m0a, d0.x); m0b = fminf(m0b, d0.y);
            m1a = fminf(m1a, d1.x); m1b = fminf(m1b, d1.y);
        }
        float sum = 2.0f * (fminf(m0a, m0b) + me0.w)
                  + 2.0f * (fminf(m1a, m1b) + me1.w);

        pm[tid] = sum;
        __syncthreads();
        for (int off = 128; off > 0; off >>= 1) {
            if (tid < off) pm[tid] += pm[tid + off];
            __syncthreads();
        }
        if (tid == 0) {
            double v = (double)pm[0];
            if (v < 0.0) v = 0.0;
            atomicAdd(&g_sacc, (ull)(v * 4294967296.0));
        }
    }

    // -------- global completion: last of all 384 blocks writes output ------
    __syncthreads();
    if (tid == 0) {
        __threadfence();
        uint32_t t = atomicAdd(&g_done, 1u);
        isLastG = (t == DGRID - 1u);
    }
    __syncthreads();
    if (isLastG && tid == 0) {
        __threadfence();
        double s = (double)g_sacc * (1.0 / 4294967296.0);
        double v = (double)g_vacc * (1.0 / 4294967296.0);
        outp[0] = (float)(s / (double)(NB * NSAMP)) +
                  (float)(v / (double)(NB * NV));
        g_sacc = 0ull;                         // restore for next replay
        g_vacc = 0ull;
        g_done = 0u;
    }
}

// ======================== launch ========================
extern "C" void kernel_launch(void* const* d_in, const int* in_sizes, int n_in,
                              void* d_out, int out_size) {
    const float* real   = (const float*)d_in[0];
    // d_in[1] synth unused, d_in[3] faces unused
    const float* verts  = (const float*)d_in[2];
    const float* center = (const float*)d_in[4];
    const float* Mmat   = (const float*)d_in[5];
    const float* cube   = (const float*)d_in[6];

    kSel<<<NB, NT>>>(real, center, Mmat, cube);
    k_dist<<<DGRID, 256>>>(verts, (float*)d_out);
}